// round 4
// baseline (speedup 1.0000x reference)
#include <cuda_runtime.h>
#include <math.h>

#define NAn 40000
#define NBn 40000
#define Hh  8
#define Cc  32
#define Dd  256
#define Ee  400000

// ---------------- device scratch (module globals; no runtime allocation) ----
__device__ __align__(256) float g_hA[(size_t)NAn * Dd];
__device__ __align__(256) float g_hB[(size_t)NBn * Dd];
__device__ __align__(256) float g_rel_ba[(size_t)NAn * Dd];
__device__ __align__(256) float g_rel_aa[(size_t)NAn * Dd];
__device__ __align__(256) float g_rel_ab[(size_t)NBn * Dd];
__device__ __align__(256) float g_al0[NAn * Hh];   // h_A . attn_l[0]
__device__ __align__(256) float g_ar1[NAn * Hh];   // h_A . attn_r[1]
__device__ __align__(256) float g_al2[NAn * Hh];   // h_A . attn_l[2]
__device__ __align__(256) float g_ar2[NAn * Hh];   // h_A . attn_r[2]
__device__ __align__(256) float g_ar0[NBn * Hh];   // h_B . attn_r[0]
__device__ __align__(256) float g_al1[NBn * Hh];   // h_B . attn_l[1]
__device__ __align__(256) float g_d_ba[NAn * Hh];
__device__ __align__(256) float g_d_aa[NAn * Hh];
__device__ __align__(256) float g_d_ab[NBn * Hh];

// ---------------- helpers ---------------------------------------------------
__device__ __forceinline__ float leaky(float x) { return x >= 0.f ? x : 0.2f * x; }
__device__ __forceinline__ float dot4(float4 a, float4 b) {
    return a.x * b.x + a.y * b.y + a.z * b.z + a.w * b.w;
}
__device__ __forceinline__ void red_add4(float* p, float a, float b, float c, float d) {
    asm volatile("red.global.add.v4.f32 [%0], {%1, %2, %3, %4};"
                 :: "l"(p), "f"(a), "f"(b), "f"(c), "f"(d)
                 : "memory");
}

// ---------------- init: zero accumulators -----------------------------------
__global__ void k_init() {
    int i = blockIdx.x * blockDim.x + threadIdx.x;
    int stride = gridDim.x * blockDim.x;
    const int n4 = (NAn * Dd) / 4;
    float4 z = make_float4(0.f, 0.f, 0.f, 0.f);
    for (int t = i; t < n4; t += stride) {
        ((float4*)g_rel_ba)[t] = z;
        ((float4*)g_rel_aa)[t] = z;
        ((float4*)g_rel_ab)[t] = z;
    }
    for (int t = i; t < NAn * Hh; t += stride) {
        g_d_ba[t] = 0.f; g_d_aa[t] = 0.f; g_d_ab[t] = 0.f;
    }
}

// ---------------- GEMM: H = X @ W + b  (M x 256 x 256) ----------------------
// 64x64 block tile, BK=16, 256 threads, 4x4 per thread.
__global__ void __launch_bounds__(256) k_gemm(const float* __restrict__ X,
                                              const float* __restrict__ W,
                                              const float* __restrict__ bias,
                                              int which) {
    float* Hout = which ? g_hB : g_hA;
    __shared__ float As[16][64];
    __shared__ float Bs[16][64];
    const int tid = threadIdx.x;
    const int bm = blockIdx.y * 64;
    const int bn = blockIdx.x * 64;
    const int tx = tid & 15;
    const int ty = tid >> 4;

    float acc[4][4];
#pragma unroll
    for (int i = 0; i < 4; i++)
#pragma unroll
        for (int j = 0; j < 4; j++) acc[i][j] = 0.f;

    const int ar = tid >> 2;          // 0..63 row within tile
    const int akc = (tid & 3) * 4;    // 0..12 k offset
    const int bk = tid >> 4;          // 0..15 k row
    const int bnc = (tid & 15) * 4;   // 0..60 n offset

    for (int k0 = 0; k0 < Dd; k0 += 16) {
        float4 a = *(const float4*)&X[(size_t)(bm + ar) * Dd + k0 + akc];
        As[akc + 0][ar] = a.x;
        As[akc + 1][ar] = a.y;
        As[akc + 2][ar] = a.z;
        As[akc + 3][ar] = a.w;
        float4 b = *(const float4*)&W[(size_t)(k0 + bk) * Dd + bn + bnc];
        *(float4*)&Bs[bk][bnc] = b;
        __syncthreads();
#pragma unroll
        for (int k = 0; k < 16; k++) {
            float4 av = *(float4*)&As[k][ty * 4];
            float4 bv = *(float4*)&Bs[k][tx * 4];
            acc[0][0] += av.x * bv.x; acc[0][1] += av.x * bv.y;
            acc[0][2] += av.x * bv.z; acc[0][3] += av.x * bv.w;
            acc[1][0] += av.y * bv.x; acc[1][1] += av.y * bv.y;
            acc[1][2] += av.y * bv.z; acc[1][3] += av.y * bv.w;
            acc[2][0] += av.z * bv.x; acc[2][1] += av.z * bv.y;
            acc[2][2] += av.z * bv.z; acc[2][3] += av.z * bv.w;
            acc[3][0] += av.w * bv.x; acc[3][1] += av.w * bv.y;
            acc[3][2] += av.w * bv.z; acc[3][3] += av.w * bv.w;
        }
        __syncthreads();
    }

    float4 bb = *(const float4*)&bias[bn + tx * 4];
#pragma unroll
    for (int i = 0; i < 4; i++) {
        int row = bm + ty * 4 + i;
        float4 o = make_float4(acc[i][0] + bb.x, acc[i][1] + bb.y,
                               acc[i][2] + bb.z, acc[i][3] + bb.w);
        *(float4*)&Hout[(size_t)row * Dd + bn + tx * 4] = o;
    }
}

// ---------------- per-node attention scalars --------------------------------
__global__ void __launch_bounds__(256) k_alpha_A(const float* __restrict__ attn_l,
                                                 const float* __restrict__ attn_r) {
    __shared__ float s0[256], s1[256], s2[256], s3[256];
    int tid = threadIdx.x;
    s0[tid] = attn_l[tid];        // mp0 attn_l
    s1[tid] = attn_r[256 + tid];  // mp1 attn_r
    s2[tid] = attn_l[512 + tid];  // mp2 attn_l
    s3[tid] = attn_r[512 + tid];  // mp2 attn_r
    __syncthreads();
    int t = blockIdx.x * 256 + tid;
    if (t >= NAn * Hh) return;
    int n = t >> 3, h = t & 7;
    const float* hp = g_hA + (size_t)n * Dd + h * Cc;
    float d0 = 0.f, d1 = 0.f, d2 = 0.f, d3 = 0.f;
#pragma unroll
    for (int i = 0; i < 8; i++) {
        float4 v = *(const float4*)(hp + i * 4);
        int b = h * Cc + i * 4;
        d0 += v.x * s0[b] + v.y * s0[b + 1] + v.z * s0[b + 2] + v.w * s0[b + 3];
        d1 += v.x * s1[b] + v.y * s1[b + 1] + v.z * s1[b + 2] + v.w * s1[b + 3];
        d2 += v.x * s2[b] + v.y * s2[b + 1] + v.z * s2[b + 2] + v.w * s2[b + 3];
        d3 += v.x * s3[b] + v.y * s3[b + 1] + v.z * s3[b + 2] + v.w * s3[b + 3];
    }
    g_al0[t] = d0; g_ar1[t] = d1; g_al2[t] = d2; g_ar2[t] = d3;
}

__global__ void __launch_bounds__(256) k_alpha_B(const float* __restrict__ attn_l,
                                                 const float* __restrict__ attn_r) {
    __shared__ float s0[256], s1[256];
    int tid = threadIdx.x;
    s0[tid] = attn_r[tid];        // mp0 attn_r
    s1[tid] = attn_l[256 + tid];  // mp1 attn_l
    __syncthreads();
    int t = blockIdx.x * 256 + tid;
    if (t >= NBn * Hh) return;
    int n = t >> 3, h = t & 7;
    const float* hp = g_hB + (size_t)n * Dd + h * Cc;
    float d0 = 0.f, d1 = 0.f;
#pragma unroll
    for (int i = 0; i < 8; i++) {
        float4 v = *(const float4*)(hp + i * 4);
        int b = h * Cc + i * 4;
        d0 += v.x * s0[b] + v.y * s0[b + 1] + v.z * s0[b + 2] + v.w * s0[b + 3];
        d1 += v.x * s1[b] + v.y * s1[b + 1] + v.z * s1[b + 2] + v.w * s1[b + 3];
    }
    g_ar0[t] = d0; g_al1[t] = d1;
}

// ---------------- edge aggregation (warp per edge) --------------------------
// rid: 0 = ba (src B -> dst A), 1 = aa, 2 = ab (src A -> dst B)
// No max-shift: |e| <= ~6 so exp(e) is numerically safe; alpha identical.
__global__ void __launch_bounds__(256) k_edge(const int* __restrict__ edge, int rid) {
    const float *al, *ar, *Hs;
    float *rel, *den;
    if (rid == 0)      { al = g_al1; ar = g_ar1; Hs = g_hB; rel = g_rel_ba; den = g_d_ba; }
    else if (rid == 1) { al = g_al2; ar = g_ar2; Hs = g_hA; rel = g_rel_aa; den = g_d_aa; }
    else               { al = g_al0; ar = g_ar0; Hs = g_hA; rel = g_rel_ab; den = g_d_ab; }

    int gw = (blockIdx.x * 256 + threadIdx.x) >> 5;
    if (gw >= Ee) return;
    int lane = threadIdx.x & 31;
    int s = __ldg(&edge[gw]);
    int d = __ldg(&edge[Ee + gw]);
    int h = lane >> 2;

    float e = __ldg(&al[s * Hh + h]) + __ldg(&ar[d * Hh + h]);
    e = leaky(e);
    float ex = __expf(e);
    if ((lane & 3) == 0) atomicAdd(&den[d * Hh + h], ex);

    const float4* hp = (const float4*)(Hs + (size_t)s * Dd + lane * 8);
    float4 v0 = __ldg(hp);
    float4 v1 = __ldg(hp + 1);
    float* rp = rel + (size_t)d * Dd + lane * 8;
    red_add4(rp,     v0.x * ex, v0.y * ex, v0.z * ex, v0.w * ex);
    red_add4(rp + 4, v1.x * ex, v1.y * ex, v1.z * ex, v1.w * ex);
}

// ---------------- finalize: normalize + beta combine + relu -----------------
// warp per node; lane covers (h = lane>>2, 8 channels at (lane&3)*8)
__global__ void __launch_bounds__(256) k_final_A(const float* __restrict__ rel_l,
                                                 const float* __restrict__ rel_r,
                                                 float* __restrict__ out) {
    int gw = (blockIdx.x * 256 + threadIdx.x) >> 5;
    if (gw >= NAn) return;
    int lane = threadIdx.x & 31;
    int n = gw;
    int off = lane * 8;       // == h*32 + (lane&3)*8
    int h = lane >> 2;
    size_t base = (size_t)n * Dd + off;

    float4 h0 = *(const float4*)(g_hA + base);
    float4 h1 = *(const float4*)(g_hA + base + 4);
    float dba = g_d_ba[n * Hh + h];
    float daa = g_d_aa[n * Hh + h];
    float i0 = dba > 0.f ? 1.f / dba : 0.f;
    float i1 = daa > 0.f ? 1.f / daa : 0.f;
    float4 e00 = *(const float4*)(g_rel_ba + base);
    float4 e01 = *(const float4*)(g_rel_ba + base + 4);
    float4 e10 = *(const float4*)(g_rel_aa + base);
    float4 e11 = *(const float4*)(g_rel_aa + base + 4);
    e00.x *= i0; e00.y *= i0; e00.z *= i0; e00.w *= i0;
    e01.x *= i0; e01.y *= i0; e01.z *= i0; e01.w *= i0;
    e10.x *= i1; e10.y *= i1; e10.z *= i1; e10.w *= i1;
    e11.x *= i1; e11.y *= i1; e11.z *= i1; e11.w *= i1;

    float4 rl0 = *(const float4*)(rel_l + off);
    float4 rl1 = *(const float4*)(rel_l + off + 4);
    float4 rr0 = *(const float4*)(rel_r + off);
    float4 rr1 = *(const float4*)(rel_r + off + 4);

    float bl = dot4(h0, rl0) + dot4(h1, rl1);
    float b0 = dot4(e00, rr0) + dot4(e01, rr1);
    float b1 = dot4(e10, rr0) + dot4(e11, rr1);
    float b2 = dot4(h0, rr0) + dot4(h1, rr1);
#define QR(v) v += __shfl_xor_sync(0xffffffffu, v, 1); v += __shfl_xor_sync(0xffffffffu, v, 2);
    QR(bl) QR(b0) QR(b1) QR(b2)

    float s0 = leaky(bl + b0), s1 = leaky(bl + b1), s2 = leaky(bl + b2);
    float mx = fmaxf(s0, fmaxf(s1, s2));
    float w0 = __expf(s0 - mx), w1 = __expf(s1 - mx), w2 = __expf(s2 - mx);
    float inv = 1.f / (w0 + w1 + w2);
    w0 *= inv; w1 *= inv; w2 *= inv;

    float4 o0, o1;
    o0.x = fmaxf(e00.x * w0 + e10.x * w1 + h0.x * w2, 0.f);
    o0.y = fmaxf(e00.y * w0 + e10.y * w1 + h0.y * w2, 0.f);
    o0.z = fmaxf(e00.z * w0 + e10.z * w1 + h0.z * w2, 0.f);
    o0.w = fmaxf(e00.w * w0 + e10.w * w1 + h0.w * w2, 0.f);
    o1.x = fmaxf(e01.x * w0 + e11.x * w1 + h1.x * w2, 0.f);
    o1.y = fmaxf(e01.y * w0 + e11.y * w1 + h1.y * w2, 0.f);
    o1.z = fmaxf(e01.z * w0 + e11.z * w1 + h1.z * w2, 0.f);
    o1.w = fmaxf(e01.w * w0 + e11.w * w1 + h1.w * w2, 0.f);
    *(float4*)(out + base) = o0;
    *(float4*)(out + base + 4) = o1;
}

__global__ void __launch_bounds__(256) k_final_B(const float* __restrict__ rel_l,
                                                 const float* __restrict__ rel_r,
                                                 float* __restrict__ out) {
    int gw = (blockIdx.x * 256 + threadIdx.x) >> 5;
    if (gw >= NBn) return;
    int lane = threadIdx.x & 31;
    int n = gw;
    int off = lane * 8;
    int h = lane >> 2;
    size_t base = (size_t)n * Dd + off;

    float4 h0 = *(const float4*)(g_hB + base);
    float4 h1 = *(const float4*)(g_hB + base + 4);
    float dab = g_d_ab[n * Hh + h];
    float i0 = dab > 0.f ? 1.f / dab : 0.f;
    float4 e00 = *(const float4*)(g_rel_ab + base);
    float4 e01 = *(const float4*)(g_rel_ab + base + 4);
    e00.x *= i0; e00.y *= i0; e00.z *= i0; e00.w *= i0;
    e01.x *= i0; e01.y *= i0; e01.z *= i0; e01.w *= i0;

    float4 rl0 = *(const float4*)(rel_l + off);
    float4 rl1 = *(const float4*)(rel_l + off + 4);
    float4 rr0 = *(const float4*)(rel_r + off);
    float4 rr1 = *(const float4*)(rel_r + off + 4);

    float bl = dot4(h0, rl0) + dot4(h1, rl1);
    float b0 = dot4(e00, rr0) + dot4(e01, rr1);
    float b1 = dot4(h0, rr0) + dot4(h1, rr1);
    QR(bl) QR(b0) QR(b1)

    float s0 = leaky(bl + b0), s1 = leaky(bl + b1);
    float mx = fmaxf(s0, s1);
    float w0 = __expf(s0 - mx), w1 = __expf(s1 - mx);
    float inv = 1.f / (w0 + w1);
    w0 *= inv; w1 *= inv;

    float4 o0, o1;
    o0.x = fmaxf(e00.x * w0 + h0.x * w1, 0.f);
    o0.y = fmaxf(e00.y * w0 + h0.y * w1, 0.f);
    o0.z = fmaxf(e00.z * w0 + h0.z * w1, 0.f);
    o0.w = fmaxf(e00.w * w0 + h0.w * w1, 0.f);
    o1.x = fmaxf(e01.x * w0 + h1.x * w1, 0.f);
    o1.y = fmaxf(e01.y * w0 + h1.y * w1, 0.f);
    o1.z = fmaxf(e01.z * w0 + h1.z * w1, 0.f);
    o1.w = fmaxf(e01.w * w0 + h1.w * w1, 0.f);
    size_t obase = (size_t)(NAn + n) * Dd + off;
    *(float4*)(out + obase) = o0;
    *(float4*)(out + obase + 4) = o1;
}

// ---------------- launch -----------------------------------------------------
extern "C" void kernel_launch(void* const* d_in, const int* in_sizes, int n_in,
                              void* d_out, int out_size) {
    const float* xA     = (const float*)d_in[0];
    const float* xB     = (const float*)d_in[1];
    const int*   e_ab   = (const int*)d_in[2];
    const int*   e_ba   = (const int*)d_in[3];
    const int*   e_aa   = (const int*)d_in[4];
    const float* WA     = (const float*)d_in[5];
    const float* bA     = (const float*)d_in[6];
    const float* WB     = (const float*)d_in[7];
    const float* bB     = (const float*)d_in[8];
    const float* attn_l = (const float*)d_in[9];
    const float* attn_r = (const float*)d_in[10];
    const float* rlA    = (const float*)d_in[11];
    const float* rrA    = (const float*)d_in[12];
    const float* rlB    = (const float*)d_in[13];
    const float* rrB    = (const float*)d_in[14];
    float* out = (float*)d_out;

    k_init<<<2048, 256>>>();
    k_gemm<<<dim3(4, 625), 256>>>(xA, WA, bA, 0);
    k_gemm<<<dim3(4, 625), 256>>>(xB, WB, bB, 1);
    k_alpha_A<<<(NAn * Hh + 255) / 256, 256>>>(attn_l, attn_r);
    k_alpha_B<<<(NBn * Hh + 255) / 256, 256>>>(attn_l, attn_r);
    k_edge<<<(Ee * 32 + 255) / 256, 256>>>(e_ba, 0);
    k_edge<<<(Ee * 32 + 255) / 256, 256>>>(e_aa, 1);
    k_edge<<<(Ee * 32 + 255) / 256, 256>>>(e_ab, 2);
    k_final_A<<<(NAn * 32 + 255) / 256, 256>>>(rlA, rrA, out);
    k_final_B<<<(NBn * 32 + 255) / 256, 256>>>(rlB, rrB, out);
}